// round 3
// baseline (speedup 1.0000x reference)
#include <cuda_runtime.h>
#include <cuda_bf16.h>
#include <cstdint>

// Problem constants (registry shapes are fixed for this problem)
#define C_IMG 512
#define C_PT  256
#define MAX_M (8 * 48 * 160)   // BS*H*W = 61440 pixels

// Scratch (static device allocations are allowed; runtime allocs are not)
__device__ float g_G[(size_t)MAX_M * C_PT];   // 61440 x 256 fp32 = 62.9 MB
__device__ float g_Wt[C_IMG * C_PT];          // W^T: [512][256], 512 KB

// ---------------------------------------------------------------------------
// Phase 0: transpose align_w (256x512) -> Wt (512x256) so GEMM B-loads coalesce
// ---------------------------------------------------------------------------
__global__ void transpose_w(const float* __restrict__ W) {
    __shared__ float tile[32][33];
    int kb = blockIdx.x * 32;   // k block
    int cb = blockIdx.y * 32;   // c block
    int tx = threadIdx.x;       // 0..31
    int ty = threadIdx.y;       // 0..7
    #pragma unroll
    for (int i = ty; i < 32; i += 8)
        tile[i][tx] = W[(size_t)(cb + i) * C_IMG + kb + tx];
    __syncthreads();
    #pragma unroll
    for (int i = ty; i < 32; i += 8)
        g_Wt[(size_t)(kb + i) * C_PT + cb + tx] = tile[tx][i];
}

// ---------------------------------------------------------------------------
// Phase 1: G[p, c'] = sum_c img[b, c, hw] * W[c', c]
// Dense SGEMM: M = BS*HW (61440), N = 256, K = 512.
// img_feat is channel-major => A is naturally K-major (As[k][m] loads coalesce).
// 128x128 block tile, BK=8, 8x8 microtile, smem double buffering.
// ---------------------------------------------------------------------------
__global__ __launch_bounds__(256, 2) void gemm_img(const float* __restrict__ A, int HW) {
    __shared__ __align__(16) float As[2][8][128];
    __shared__ __align__(16) float Bs[2][8][128];

    const int tid = threadIdx.x;
    const int lk = tid >> 5;           // 0..7   (k row for loads)
    const int lm = (tid & 31) << 2;    // 0..124 (vec4 col for loads)
    const int ty = tid >> 4;           // 0..15  (pixel sub-tile)
    const int tx = tid & 15;           // 0..15  (channel sub-tile)

    const int pm0 = blockIdx.x * 128;  // global pixel base (stays within one batch: HW%128==0)
    const int cn0 = blockIdx.y * 128;  // output channel base
    const int b   = pm0 / HW;

    // element (m, c) of A lives at (b*C_IMG + c)*HW + (pm0 - b*HW) + m
    const float* Abase = A + (size_t)b * (C_IMG - 1) * HW + pm0 + lm;
    const float* Bbase = g_Wt + cn0 + lm;

    float4 av = *reinterpret_cast<const float4*>(Abase + (size_t)lk * HW);
    float4 bv = *reinterpret_cast<const float4*>(Bbase + (size_t)lk * C_PT);
    *reinterpret_cast<float4*>(&As[0][lk][lm]) = av;
    *reinterpret_cast<float4*>(&Bs[0][lk][lm]) = bv;
    __syncthreads();

    float acc[8][8];
    #pragma unroll
    for (int i = 0; i < 8; i++)
        #pragma unroll
        for (int j = 0; j < 8; j++) acc[i][j] = 0.f;

    int buf = 0;
    for (int k0 = 0; k0 < C_IMG; k0 += 8) {
        const bool has_next = (k0 + 8) < C_IMG;
        if (has_next) {
            av = *reinterpret_cast<const float4*>(Abase + (size_t)(k0 + 8 + lk) * HW);
            bv = *reinterpret_cast<const float4*>(Bbase + (size_t)(k0 + 8 + lk) * C_PT);
        }
        #pragma unroll
        for (int k = 0; k < 8; k++) {
            float ar[8], br[8];
            *reinterpret_cast<float4*>(ar)     = *reinterpret_cast<float4*>(&As[buf][k][ty * 8]);
            *reinterpret_cast<float4*>(ar + 4) = *reinterpret_cast<float4*>(&As[buf][k][ty * 8 + 4]);
            *reinterpret_cast<float4*>(br)     = *reinterpret_cast<float4*>(&Bs[buf][k][tx * 8]);
            *reinterpret_cast<float4*>(br + 4) = *reinterpret_cast<float4*>(&Bs[buf][k][tx * 8 + 4]);
            #pragma unroll
            for (int i = 0; i < 8; i++)
                #pragma unroll
                for (int j = 0; j < 8; j++)
                    acc[i][j] = fmaf(ar[i], br[j], acc[i][j]);
        }
        if (has_next) {
            buf ^= 1;
            *reinterpret_cast<float4*>(&As[buf][lk][lm]) = av;
            *reinterpret_cast<float4*>(&Bs[buf][lk][lm]) = bv;
            __syncthreads();
        }
    }

    #pragma unroll
    for (int i = 0; i < 8; i++) {
        float* gp = g_G + (size_t)(pm0 + ty * 8 + i) * C_PT + cn0 + tx * 8;
        float4 v0 = make_float4(acc[i][0], acc[i][1], acc[i][2], acc[i][3]);
        float4 v1 = make_float4(acc[i][4], acc[i][5], acc[i][6], acc[i][7]);
        *reinterpret_cast<float4*>(gp)     = v0;
        *reinterpret_cast<float4*>(gp + 4) = v1;
    }
}

// ---------------------------------------------------------------------------
// Phase 2: per-point projection + bilinear blend of precomputed G + bias + pf
// 64 threads per point (4 channels each via float4), 4 points per block.
// ---------------------------------------------------------------------------
__global__ void fuse_kernel(
    const float* __restrict__ pf,
    const float* __restrict__ centers,
    const float* __restrict__ P2,
    const float* __restrict__ R0,
    const float* __restrict__ Tr,
    const float* __restrict__ ab,
    const int*   __restrict__ bidx,
    const int*   __restrict__ hp,
    const int*   __restrict__ wp,
    float*       __restrict__ out,
    int N)
{
    const int tid  = threadIdx.x;
    const int grp  = tid >> 6;       // 0..3
    const int lane = tid & 63;       // 0..63 -> 4 channels each
    const int n = blockIdx.x * 4 + grp;
    if (n >= N) return;

    const int b = bidx[n];
    const float px = centers[n * 3 + 0];
    const float py = centers[n * 3 + 1];
    const float pz = centers[n * 3 + 2];

    const float* tr = Tr + (size_t)b * 16;
    const float c0 = tr[0]  * px + tr[1]  * py + tr[2]  * pz + tr[3];
    const float c1 = tr[4]  * px + tr[5]  * py + tr[6]  * pz + tr[7];
    const float c2 = tr[8]  * px + tr[9]  * py + tr[10] * pz + tr[11];
    const float c3 = tr[12] * px + tr[13] * py + tr[14] * pz + tr[15];

    const float* r = R0 + (size_t)b * 16;
    const float e0 = r[0]  * c0 + r[1]  * c1 + r[2]  * c2 + r[3]  * c3;
    const float e1 = r[4]  * c0 + r[5]  * c1 + r[6]  * c2 + r[7]  * c3;
    const float e2 = r[8]  * c0 + r[9]  * c1 + r[10] * c2 + r[11] * c3;
    const float e3 = r[12] * c0 + r[13] * c1 + r[14] * c2 + r[15] * c3;

    const float* pm = P2 + (size_t)b * 12;
    const float iu = pm[0] * e0 + pm[1] * e1 + pm[2]  * e2 + pm[3]  * e3;
    const float iv = pm[4] * e0 + pm[5] * e1 + pm[6]  * e2 + pm[7]  * e3;
    const float iz = pm[8] * e0 + pm[9] * e1 + pm[10] * e2 + pm[11] * e3;

    const float depth = fmaxf(iz, 1e-5f);
    const float u = iu / depth;
    const float v = iv / depth;

    const int Wf = wp[0];
    const int Hf = hp[0];
    const bool valid = (iz > 0.f) && (u >= 0.f) && (u < (float)Wf) &&
                       (v >= 0.f) && (v < (float)Hf);

    const float x0f = floorf(u), y0f = floorf(v);
    const float wx1 = u - x0f, wx0 = 1.f - wx1;
    const float wy1 = v - y0f, wy0 = 1.f - wy1;
    const float vw = valid ? 1.f : 0.f;

    const float x1f = x0f + 1.f, y1f = y0f + 1.f;
    const bool bx0 = (x0f >= 0.f) && (x0f <= (float)(Wf - 1));
    const bool bx1 = (x1f >= 0.f) && (x1f <= (float)(Wf - 1));
    const bool by0 = (y0f >= 0.f) && (y0f <= (float)(Hf - 1));
    const bool by1 = (y1f >= 0.f) && (y1f <= (float)(Hf - 1));

    float w00 = wx0 * wy0 * vw * (float)(bx0 && by0);
    float w10 = wx1 * wy0 * vw * (float)(bx1 && by0);
    float w01 = wx0 * wy1 * vw * (float)(bx0 && by1);
    float w11 = wx1 * wy1 * vw * (float)(bx1 && by1);

    const int x0c = min(max((int)x0f, 0), Wf - 1);
    const int x1c = min(max((int)x0f + 1, 0), Wf - 1);
    const int y0c = min(max((int)y0f, 0), Hf - 1);
    const int y1c = min(max((int)y0f + 1, 0), Hf - 1);

    const size_t HWl = (size_t)Hf * Wf;
    const size_t base_b = (size_t)b * HWl;
    const size_t p00 = (base_b + (size_t)y0c * Wf + x0c) * C_PT;
    const size_t p10 = (base_b + (size_t)y0c * Wf + x1c) * C_PT;
    const size_t p01 = (base_b + (size_t)y1c * Wf + x0c) * C_PT;
    const size_t p11 = (base_b + (size_t)y1c * Wf + x1c) * C_PT;

    const int co = lane * 4;
    float4 acc = *reinterpret_cast<const float4*>(pf + (size_t)n * C_PT + co);
    const float4 bb = *reinterpret_cast<const float4*>(ab + co);
    acc.x += bb.x; acc.y += bb.y; acc.z += bb.z; acc.w += bb.w;

    if (w00 != 0.f) {
        const float4 g = *reinterpret_cast<const float4*>(g_G + p00 + co);
        acc.x = fmaf(w00, g.x, acc.x); acc.y = fmaf(w00, g.y, acc.y);
        acc.z = fmaf(w00, g.z, acc.z); acc.w = fmaf(w00, g.w, acc.w);
    }
    if (w10 != 0.f) {
        const float4 g = *reinterpret_cast<const float4*>(g_G + p10 + co);
        acc.x = fmaf(w10, g.x, acc.x); acc.y = fmaf(w10, g.y, acc.y);
        acc.z = fmaf(w10, g.z, acc.z); acc.w = fmaf(w10, g.w, acc.w);
    }
    if (w01 != 0.f) {
        const float4 g = *reinterpret_cast<const float4*>(g_G + p01 + co);
        acc.x = fmaf(w01, g.x, acc.x); acc.y = fmaf(w01, g.y, acc.y);
        acc.z = fmaf(w01, g.z, acc.z); acc.w = fmaf(w01, g.w, acc.w);
    }
    if (w11 != 0.f) {
        const float4 g = *reinterpret_cast<const float4*>(g_G + p11 + co);
        acc.x = fmaf(w11, g.x, acc.x); acc.y = fmaf(w11, g.y, acc.y);
        acc.z = fmaf(w11, g.z, acc.z); acc.w = fmaf(w11, g.w, acc.w);
    }

    *reinterpret_cast<float4*>(out + (size_t)n * C_PT + co) = acc;
}

// ---------------------------------------------------------------------------
// Launch
// Input order (metadata): point_feat, pillar_centers, img_feat, P2, R0, Tr,
//                         align_w, align_b, batch_idx, img_h, img_w
// ---------------------------------------------------------------------------
extern "C" void kernel_launch(void* const* d_in, const int* in_sizes, int n_in,
                              void* d_out, int out_size) {
    const float* point_feat = (const float*)d_in[0];
    const float* centers    = (const float*)d_in[1];
    const float* img        = (const float*)d_in[2];
    const float* P2         = (const float*)d_in[3];
    const float* R0         = (const float*)d_in[4];
    const float* Tr         = (const float*)d_in[5];
    const float* align_w    = (const float*)d_in[6];
    const float* align_b    = (const float*)d_in[7];
    const int*   bidx       = (const int*)d_in[8];
    const int*   img_h      = (const int*)d_in[9];
    const int*   img_w      = (const int*)d_in[10];
    float* out = (float*)d_out;

    const int N  = in_sizes[8];
    const int BS = in_sizes[3] / 12;
    const int HW = in_sizes[2] / (BS * C_IMG);
    const int M  = BS * HW;

    // Phase 0: W^T
    transpose_w<<<dim3(C_IMG / 32, C_PT / 32), dim3(32, 8)>>>(align_w);

    // Phase 1: G = img @ W^T  (per pixel)
    gemm_img<<<dim3(M / 128, C_PT / 128), 256>>>(img, HW);

    // Phase 2: gather + blend + bias + residual
    fuse_kernel<<<(N + 3) / 4, 256>>>(point_feat, centers, P2, R0, Tr,
                                      align_b, bidx, img_h, img_w, out, N);
}

// round 6
// speedup vs baseline: 2.2454x; 2.2454x over previous
#include <cuda_runtime.h>
#include <cuda_bf16.h>
#include <cstdint>

// Problem constants (fixed shapes for this problem)
#define C_IMG 512
#define C_PT  256
#define MAX_M (8 * 48 * 160)   // BS*H*W = 61440 pixels

// Static device scratch
__device__ float g_G[(size_t)MAX_M * C_PT];   // GEMM output: 61440 x 256 (62.9 MB)
__device__ float g_Wt[C_IMG * C_PT];          // W^T, tf32-rounded: [512 k][256 n]

__device__ __forceinline__ float to_tf32(float x) {
    uint32_t u;
    asm("cvt.rna.tf32.f32 %0, %1;" : "=r"(u) : "f"(x));
    return __uint_as_float(u);
}

// mma.sync tf32 m16n8k8 (sm_80+; compiles for plain sm_103)
__device__ __forceinline__ void mma_tf32(float* d, const uint32_t* a, const uint32_t* b) {
    asm volatile(
        "mma.sync.aligned.m16n8k8.row.col.f32.tf32.tf32.f32 "
        "{%0,%1,%2,%3}, {%4,%5,%6,%7}, {%8,%9}, {%0,%1,%2,%3};"
        : "+f"(d[0]), "+f"(d[1]), "+f"(d[2]), "+f"(d[3])
        : "r"(a[0]), "r"(a[1]), "r"(a[2]), "r"(a[3]),
          "r"(b[0]), "r"(b[1]));
}

// ---------------------------------------------------------------------------
// Phase 0: transpose align_w (256x512) -> g_Wt [512][256], tf32-rounded
// ---------------------------------------------------------------------------
__global__ void transpose_w(const float* __restrict__ W) {
    __shared__ float tile[32][33];
    int kb = blockIdx.x * 32;
    int cb = blockIdx.y * 32;
    int tx = threadIdx.x, ty = threadIdx.y;
    #pragma unroll
    for (int i = ty; i < 32; i += 8)
        tile[i][tx] = W[(size_t)(cb + i) * C_IMG + kb + tx];
    __syncthreads();
    #pragma unroll
    for (int i = ty; i < 32; i += 8)
        g_Wt[(size_t)(kb + i) * C_PT + cb + tx] = to_tf32(tile[tx][i]);
}

// ---------------------------------------------------------------------------
// Phase 1: G[p, n] = sum_k img[b, k, hw] * W[n, k] via mma.sync tf32.
//   Block tile 128(M) x 128(N), BK=16, 8 warps (2x4), warp tile 64x32.
//   A tile loaded straight from channel-major img (transpose happens on the
//   coalesced LDG -> As[k][m] STS). Row stride 136 floats => conflict-free
//   fragment LDS (bank = (8k + m) % 32, distinct across the quad pattern).
// ---------------------------------------------------------------------------
#define BM 128
#define BN 128
#define BK 16
#define APAD 136

__global__ __launch_bounds__(256, 2) void gemm_mma(const float* __restrict__ img, int HW) {
    __shared__ __align__(16) float As[2][BK][APAD];
    __shared__ __align__(16) float Bs[2][BK][APAD];

    const int tid  = threadIdx.x;
    const int wid  = tid >> 5;
    const int lane = tid & 31;
    const int g    = lane >> 2;     // group id 0..7
    const int tig  = lane & 3;      // thread-in-group 0..3
    const int wm   = (wid & 1) * 64;
    const int wn   = (wid >> 1) * 32;

    const int m0 = blockIdx.x * BM;
    const int n0 = blockIdx.y * BN;
    const int b  = m0 / HW;
    const int hw0 = m0 - b * HW;

    // global load mapping: thread covers 8 consecutive elements of one k-row
    const int lk = tid >> 4;          // 0..15
    const int lm = (tid & 15) * 8;    // 0..120

    const float* Abase = img + ((size_t)b * C_IMG + lk) * HW + hw0 + lm;
    const float* Bbase = g_Wt + (size_t)lk * C_PT + n0 + lm;

    float4 av0, av1, bv0, bv1;
    av0 = *reinterpret_cast<const float4*>(Abase);
    av1 = *reinterpret_cast<const float4*>(Abase + 4);
    bv0 = *reinterpret_cast<const float4*>(Bbase);
    bv1 = *reinterpret_cast<const float4*>(Bbase + 4);

    {   // stage 0 STS (A gets tf32 rounding; B already rounded)
        float* as = &As[0][lk][lm];
        as[0]=to_tf32(av0.x); as[1]=to_tf32(av0.y); as[2]=to_tf32(av0.z); as[3]=to_tf32(av0.w);
        as[4]=to_tf32(av1.x); as[5]=to_tf32(av1.y); as[6]=to_tf32(av1.z); as[7]=to_tf32(av1.w);
        *reinterpret_cast<float4*>(&Bs[0][lk][lm])     = bv0;
        *reinterpret_cast<float4*>(&Bs[0][lk][lm + 4]) = bv1;
    }
    __syncthreads();

    float acc[4][4][4];
    #pragma unroll
    for (int i = 0; i < 4; i++)
        #pragma unroll
        for (int j = 0; j < 4; j++)
            #pragma unroll
            for (int r = 0; r < 4; r++) acc[i][j][r] = 0.f;

    int buf = 0;
    for (int k0 = 0; k0 < C_IMG; k0 += BK) {
        const bool nxt = (k0 + BK) < C_IMG;
        if (nxt) {
            const float* ap = Abase + (size_t)(k0 + BK) * HW;
            const float* bp = Bbase + (size_t)(k0 + BK) * C_PT;
            av0 = *reinterpret_cast<const float4*>(ap);
            av1 = *reinterpret_cast<const float4*>(ap + 4);
            bv0 = *reinterpret_cast<const float4*>(bp);
            bv1 = *reinterpret_cast<const float4*>(bp + 4);
        }

        #pragma unroll
        for (int ks = 0; ks < BK; ks += 8) {
            uint32_t af[4][4], bf[4][2];
            #pragma unroll
            for (int mf = 0; mf < 4; mf++) {
                const int m = wm + mf * 16 + g;
                af[mf][0] = __float_as_uint(As[buf][ks + tig]    [m]);
                af[mf][1] = __float_as_uint(As[buf][ks + tig]    [m + 8]);
                af[mf][2] = __float_as_uint(As[buf][ks + tig + 4][m]);
                af[mf][3] = __float_as_uint(As[buf][ks + tig + 4][m + 8]);
            }
            #pragma unroll
            for (int nf = 0; nf < 4; nf++) {
                const int n = wn + nf * 8 + g;
                bf[nf][0] = __float_as_uint(Bs[buf][ks + tig]    [n]);
                bf[nf][1] = __float_as_uint(Bs[buf][ks + tig + 4][n]);
            }
            #pragma unroll
            for (int mf = 0; mf < 4; mf++)
                #pragma unroll
                for (int nf = 0; nf < 4; nf++)
                    mma_tf32(acc[mf][nf], af[mf], bf[nf]);
        }

        if (nxt) {
            buf ^= 1;
            float* as = &As[buf][lk][lm];
            as[0]=to_tf32(av0.x); as[1]=to_tf32(av0.y); as[2]=to_tf32(av0.z); as[3]=to_tf32(av0.w);
            as[4]=to_tf32(av1.x); as[5]=to_tf32(av1.y); as[6]=to_tf32(av1.z); as[7]=to_tf32(av1.w);
            *reinterpret_cast<float4*>(&Bs[buf][lk][lm])     = bv0;
            *reinterpret_cast<float4*>(&Bs[buf][lk][lm + 4]) = bv1;
            __syncthreads();
        }
    }

    // Epilogue: c0,c1 -> row g, cols 2tig..2tig+1 ; c2,c3 -> row g+8
    #pragma unroll
    for (int mf = 0; mf < 4; mf++) {
        const int r0 = m0 + wm + mf * 16 + g;
        #pragma unroll
        for (int nf = 0; nf < 4; nf++) {
            const int c = n0 + wn + nf * 8 + 2 * tig;
            *reinterpret_cast<float2*>(g_G + (size_t)r0 * C_PT + c) =
                make_float2(acc[mf][nf][0], acc[mf][nf][1]);
            *reinterpret_cast<float2*>(g_G + (size_t)(r0 + 8) * C_PT + c) =
                make_float2(acc[mf][nf][2], acc[mf][nf][3]);
        }
    }
}

// ---------------------------------------------------------------------------
// Phase 2: per-point projection + bilinear blend of precomputed G + bias + pf
// ---------------------------------------------------------------------------
__global__ void fuse_kernel(
    const float* __restrict__ pf,
    const float* __restrict__ centers,
    const float* __restrict__ P2,
    const float* __restrict__ R0,
    const float* __restrict__ Tr,
    const float* __restrict__ ab,
    const int*   __restrict__ bidx,
    const int*   __restrict__ hp,
    const int*   __restrict__ wp,
    float*       __restrict__ out,
    int N)
{
    const int tid  = threadIdx.x;
    const int grp  = tid >> 6;       // 0..3
    const int lane = tid & 63;       // 0..63 -> 4 channels each
    const int n = blockIdx.x * 4 + grp;
    if (n >= N) return;

    const int b = bidx[n];
    const float px = centers[n * 3 + 0];
    const float py = centers[n * 3 + 1];
    const float pz = centers[n * 3 + 2];

    const float* tr = Tr + (size_t)b * 16;
    const float c0 = tr[0]  * px + tr[1]  * py + tr[2]  * pz + tr[3];
    const float c1 = tr[4]  * px + tr[5]  * py + tr[6]  * pz + tr[7];
    const float c2 = tr[8]  * px + tr[9]  * py + tr[10] * pz + tr[11];
    const float c3 = tr[12] * px + tr[13] * py + tr[14] * pz + tr[15];

    const float* r = R0 + (size_t)b * 16;
    const float e0 = r[0]  * c0 + r[1]  * c1 + r[2]  * c2 + r[3]  * c3;
    const float e1 = r[4]  * c0 + r[5]  * c1 + r[6]  * c2 + r[7]  * c3;
    const float e2 = r[8]  * c0 + r[9]  * c1 + r[10] * c2 + r[11] * c3;
    const float e3 = r[12] * c0 + r[13] * c1 + r[14] * c2 + r[15] * c3;

    const float* pm = P2 + (size_t)b * 12;
    const float iu = pm[0] * e0 + pm[1] * e1 + pm[2]  * e2 + pm[3]  * e3;
    const float iv = pm[4] * e0 + pm[5] * e1 + pm[6]  * e2 + pm[7]  * e3;
    const float iz = pm[8] * e0 + pm[9] * e1 + pm[10] * e2 + pm[11] * e3;

    const float depth = fmaxf(iz, 1e-5f);
    const float u = iu / depth;
    const float v = iv / depth;

    const int Wf = wp[0];
    const int Hf = hp[0];
    const bool valid = (iz > 0.f) && (u >= 0.f) && (u < (float)Wf) &&
                       (v >= 0.f) && (v < (float)Hf);

    const float x0f = floorf(u), y0f = floorf(v);
    const float wx1 = u - x0f, wx0 = 1.f - wx1;
    const float wy1 = v - y0f, wy0 = 1.f - wy1;
    const float vw = valid ? 1.f : 0.f;

    const float x1f = x0f + 1.f, y1f = y0f + 1.f;
    const bool bx0 = (x0f >= 0.f) && (x0f <= (float)(Wf - 1));
    const bool bx1 = (x1f >= 0.f) && (x1f <= (float)(Wf - 1));
    const bool by0 = (y0f >= 0.f) && (y0f <= (float)(Hf - 1));
    const bool by1 = (y1f >= 0.f) && (y1f <= (float)(Hf - 1));

    float w00 = wx0 * wy0 * vw * (float)(bx0 && by0);
    float w10 = wx1 * wy0 * vw * (float)(bx1 && by0);
    float w01 = wx0 * wy1 * vw * (float)(bx0 && by1);
    float w11 = wx1 * wy1 * vw * (float)(bx1 && by1);

    const int x0c = min(max((int)x0f, 0), Wf - 1);
    const int x1c = min(max((int)x0f + 1, 0), Wf - 1);
    const int y0c = min(max((int)y0f, 0), Hf - 1);
    const int y1c = min(max((int)y0f + 1, 0), Hf - 1);

    const size_t HWl = (size_t)Hf * Wf;
    const size_t base_b = (size_t)b * HWl;
    const size_t p00 = (base_b + (size_t)y0c * Wf + x0c) * C_PT;
    const size_t p10 = (base_b + (size_t)y0c * Wf + x1c) * C_PT;
    const size_t p01 = (base_b + (size_t)y1c * Wf + x0c) * C_PT;
    const size_t p11 = (base_b + (size_t)y1c * Wf + x1c) * C_PT;

    const int co = lane * 4;
    float4 acc = *reinterpret_cast<const float4*>(pf + (size_t)n * C_PT + co);
    const float4 bb = *reinterpret_cast<const float4*>(ab + co);
    acc.x += bb.x; acc.y += bb.y; acc.z += bb.z; acc.w += bb.w;

    if (w00 != 0.f) {
        const float4 g = *reinterpret_cast<const float4*>(g_G + p00 + co);
        acc.x = fmaf(w00, g.x, acc.x); acc.y = fmaf(w00, g.y, acc.y);
        acc.z = fmaf(w00, g.z, acc.z); acc.w = fmaf(w00, g.w, acc.w);
    }
    if (w10 != 0.f) {
        const float4 g = *reinterpret_cast<const float4*>(g_G + p10 + co);
        acc.x = fmaf(w10, g.x, acc.x); acc.y = fmaf(w10, g.y, acc.y);
        acc.z = fmaf(w10, g.z, acc.z); acc.w = fmaf(w10, g.w, acc.w);
    }
    if (w01 != 0.f) {
        const float4 g = *reinterpret_cast<const float4*>(g_G + p01 + co);
        acc.x = fmaf(w01, g.x, acc.x); acc.y = fmaf(w01, g.y, acc.y);
        acc.z = fmaf(w01, g.z, acc.z); acc.w = fmaf(w01, g.w, acc.w);
    }
    if (w11 != 0.f) {
        const float4 g = *reinterpret_cast<const float4*>(g_G + p11 + co);
        acc.x = fmaf(w11, g.x, acc.x); acc.y = fmaf(w11, g.y, acc.y);
        acc.z = fmaf(w11, g.z, acc.z); acc.w = fmaf(w11, g.w, acc.w);
    }

    *reinterpret_cast<float4*>(out + (size_t)n * C_PT + co) = acc;
}

// ---------------------------------------------------------------------------
// Launch
// Input order (metadata): point_feat, pillar_centers, img_feat, P2, R0, Tr,
//                         align_w, align_b, batch_idx, img_h, img_w
// ---------------------------------------------------------------------------
extern "C" void kernel_launch(void* const* d_in, const int* in_sizes, int n_in,
                              void* d_out, int out_size) {
    const float* point_feat = (const float*)d_in[0];
    const float* centers    = (const float*)d_in[1];
    const float* img        = (const float*)d_in[2];
    const float* P2         = (const float*)d_in[3];
    const float* R0         = (const float*)d_in[4];
    const float* Tr         = (const float*)d_in[5];
    const float* align_w    = (const float*)d_in[6];
    const float* align_b    = (const float*)d_in[7];
    const int*   bidx       = (const int*)d_in[8];
    const int*   img_h      = (const int*)d_in[9];
    const int*   img_w      = (const int*)d_in[10];
    float* out = (float*)d_out;

    const int N  = in_sizes[8];
    const int BS = in_sizes[3] / 12;
    const int HW = in_sizes[2] / (BS * C_IMG);
    const int M  = BS * HW;

    // Phase 0: W^T (tf32-rounded)
    transpose_w<<<dim3(C_IMG / 32, C_PT / 32), dim3(32, 8)>>>(align_w);

    // Phase 1: G = img @ W^T via mma.sync tf32
    gemm_mma<<<dim3(M / BM, C_PT / BN), 256>>>(img, HW);

    // Phase 2: gather + blend + bias + residual
    fuse_kernel<<<(N + 3) / 4, 256>>>(point_feat, centers, P2, R0, Tr,
                                      align_b, bidx, img_h, img_w, out, N);
}

// round 7
// speedup vs baseline: 2.8243x; 1.2578x over previous
#include <cuda_runtime.h>
#include <cuda_bf16.h>
#include <cstdint>

// Problem constants (fixed shapes for this problem)
#define C_IMG 512
#define C_PT  256
#define MAX_M (8 * 48 * 160)   // BS*H*W = 61440 pixels
#define MAX_N 131072           // >= point count (100000)

// Static device scratch
__device__ float g_G[(size_t)MAX_M * C_PT];   // GEMM output: 61440 x 256 (62.9 MB)
__device__ float g_Wt[C_IMG * C_PT];          // W^T, tf32-rounded: [512 k][256 n]
__device__ float4 g_wts[MAX_N];               // per-point bilinear weights
__device__ int4   g_offs[MAX_N];              // per-point G offsets (premultiplied by C_PT)

__device__ __forceinline__ float to_tf32(float x) {
    uint32_t u;
    asm("cvt.rna.tf32.f32 %0, %1;" : "=r"(u) : "f"(x));
    return __uint_as_float(u);
}

// mma.sync tf32 m16n8k8 (sm_80+; compiles for plain sm_103)
__device__ __forceinline__ void mma_tf32(float* d, const uint32_t* a, const uint32_t* b) {
    asm volatile(
        "mma.sync.aligned.m16n8k8.row.col.f32.tf32.tf32.f32 "
        "{%0,%1,%2,%3}, {%4,%5,%6,%7}, {%8,%9}, {%0,%1,%2,%3};"
        : "+f"(d[0]), "+f"(d[1]), "+f"(d[2]), "+f"(d[3])
        : "r"(a[0]), "r"(a[1]), "r"(a[2]), "r"(a[3]),
          "r"(b[0]), "r"(b[1]));
}

__device__ __forceinline__ void cp16(uint32_t smem_dst, const void* gsrc) {
    asm volatile("cp.async.ca.shared.global [%0], [%1], 16;"
                 :: "r"(smem_dst), "l"(gsrc) : "memory");
}

// ---------------------------------------------------------------------------
// Phase 0: transpose align_w (256x512) -> g_Wt [512][256], tf32-rounded
// ---------------------------------------------------------------------------
__global__ void transpose_w(const float* __restrict__ W) {
    __shared__ float tile[32][33];
    int kb = blockIdx.x * 32;
    int cb = blockIdx.y * 32;
    int tx = threadIdx.x, ty = threadIdx.y;
    #pragma unroll
    for (int i = ty; i < 32; i += 8)
        tile[i][tx] = W[(size_t)(cb + i) * C_IMG + kb + tx];
    __syncthreads();
    #pragma unroll
    for (int i = ty; i < 32; i += 8)
        g_Wt[(size_t)(kb + i) * C_PT + cb + tx] = to_tf32(tile[tx][i]);
}

// ---------------------------------------------------------------------------
// Phase 1: G[p, n] = sum_k img[b, k, hw] * W[n, k] via mma.sync tf32.
//   Block tile 128(M) x 128(N), BK=16, 8 warps (2x4), warp tile 64x32.
//   3-stage cp.async pipeline. A loaded raw (tf32 HW truncation); B is
//   rna-rounded in transpose_w. Row stride 136 floats => conflict-free LDS.
// ---------------------------------------------------------------------------
#define BM 128
#define BN 128
#define BK 16
#define APAD 136
#define NSTAGE 3
#define NCHUNK (C_IMG / BK)                // 32
#define STAGE_FLOATS (BK * APAD)           // 2176 floats = 8704 B
#define GEMM_SMEM (NSTAGE * 2 * STAGE_FLOATS * 4)   // 52224 B

__global__ __launch_bounds__(256, 2) void gemm_mma(const float* __restrict__ img, int HW) {
    extern __shared__ __align__(16) float dsm[];
    float* As = dsm;                               // [NSTAGE][BK][APAD]
    float* Bs = dsm + NSTAGE * STAGE_FLOATS;       // [NSTAGE][BK][APAD]

    const int tid  = threadIdx.x;
    const int wid  = tid >> 5;
    const int lane = tid & 31;
    const int g    = lane >> 2;     // group id 0..7
    const int tig  = lane & 3;      // thread-in-group 0..3
    const int wm   = (wid & 1) * 64;
    const int wn   = (wid >> 1) * 32;

    const int m0 = blockIdx.x * BM;
    const int n0 = blockIdx.y * BN;
    const int b  = m0 / HW;
    const int hw0 = m0 - b * HW;

    // global load mapping: thread covers 8 consecutive elements of one k-row
    const int lk = tid >> 4;          // 0..15
    const int lm = (tid & 15) * 8;    // 0..120

    const float* Abase = img + ((size_t)b * C_IMG + lk) * HW + hw0 + lm;
    const float* Bbase = g_Wt + (size_t)lk * C_PT + n0 + lm;

    const uint32_t sa = (uint32_t)__cvta_generic_to_shared(As) + (uint32_t)(lk * APAD + lm) * 4u;
    const uint32_t sb = (uint32_t)__cvta_generic_to_shared(Bs) + (uint32_t)(lk * APAD + lm) * 4u;

    // prologue: stages 0 and 1
    #pragma unroll
    for (int s = 0; s < 2; s++) {
        const float* ap = Abase + (size_t)(s * BK) * HW;
        const float* bp = Bbase + (size_t)(s * BK) * C_PT;
        const uint32_t da = sa + s * (STAGE_FLOATS * 4);
        const uint32_t db = sb + s * (STAGE_FLOATS * 4);
        cp16(da,      ap);
        cp16(da + 16, ap + 4);
        cp16(db,      bp);
        cp16(db + 16, bp + 4);
        asm volatile("cp.async.commit_group;" ::: "memory");
    }

    float acc[4][4][4];
    #pragma unroll
    for (int i = 0; i < 4; i++)
        #pragma unroll
        for (int j = 0; j < 4; j++)
            #pragma unroll
            for (int r = 0; r < 4; r++) acc[i][j][r] = 0.f;

    for (int i = 0; i < NCHUNK; i++) {
        const int buf = i % NSTAGE;

        if (i < NCHUNK - 1) {
            asm volatile("cp.async.wait_group 1;" ::: "memory");
        } else {
            asm volatile("cp.async.wait_group 0;" ::: "memory");
        }
        __syncthreads();   // stage i visible to all warps; chunk i-1 compute done

        if (i + 2 < NCHUNK) {
            const int s = (i + 2) % NSTAGE;
            const float* ap = Abase + (size_t)((i + 2) * BK) * HW;
            const float* bp = Bbase + (size_t)((i + 2) * BK) * C_PT;
            const uint32_t da = sa + s * (STAGE_FLOATS * 4);
            const uint32_t db = sb + s * (STAGE_FLOATS * 4);
            cp16(da,      ap);
            cp16(da + 16, ap + 4);
            cp16(db,      bp);
            cp16(db + 16, bp + 4);
            asm volatile("cp.async.commit_group;" ::: "memory");
        }

        const float* as = As + buf * STAGE_FLOATS;
        const float* bs = Bs + buf * STAGE_FLOATS;
        #pragma unroll
        for (int ks = 0; ks < BK; ks += 8) {
            uint32_t af[4][4], bf[4][2];
            #pragma unroll
            for (int mf = 0; mf < 4; mf++) {
                const int m = wm + mf * 16 + g;
                af[mf][0] = __float_as_uint(as[(ks + tig)     * APAD + m]);
                af[mf][1] = __float_as_uint(as[(ks + tig)     * APAD + m + 8]);
                af[mf][2] = __float_as_uint(as[(ks + tig + 4) * APAD + m]);
                af[mf][3] = __float_as_uint(as[(ks + tig + 4) * APAD + m + 8]);
            }
            #pragma unroll
            for (int nf = 0; nf < 4; nf++) {
                const int n = wn + nf * 8 + g;
                bf[nf][0] = __float_as_uint(bs[(ks + tig)     * APAD + n]);
                bf[nf][1] = __float_as_uint(bs[(ks + tig + 4) * APAD + n]);
            }
            #pragma unroll
            for (int mf = 0; mf < 4; mf++)
                #pragma unroll
                for (int nf = 0; nf < 4; nf++)
                    mma_tf32(acc[mf][nf], af[mf], bf[nf]);
        }
    }

    // Epilogue: c0,c1 -> row g, cols 2tig..2tig+1 ; c2,c3 -> row g+8
    #pragma unroll
    for (int mf = 0; mf < 4; mf++) {
        const int r0 = m0 + wm + mf * 16 + g;
        #pragma unroll
        for (int nf = 0; nf < 4; nf++) {
            const int c = n0 + wn + nf * 8 + 2 * tig;
            *reinterpret_cast<float2*>(g_G + (size_t)r0 * C_PT + c) =
                make_float2(acc[mf][nf][0], acc[mf][nf][1]);
            *reinterpret_cast<float2*>(g_G + (size_t)(r0 + 8) * C_PT + c) =
                make_float2(acc[mf][nf][2], acc[mf][nf][3]);
        }
    }
}

// ---------------------------------------------------------------------------
// Phase 2a: per-point projection -> weights + premultiplied G offsets
// ---------------------------------------------------------------------------
__global__ void proj_kernel(
    const float* __restrict__ centers,
    const float* __restrict__ P2,
    const float* __restrict__ R0,
    const float* __restrict__ Tr,
    const int*   __restrict__ bidx,
    const int*   __restrict__ hp,
    const int*   __restrict__ wp,
    int N)
{
    const int n = blockIdx.x * 256 + threadIdx.x;
    if (n >= N) return;

    const int b = bidx[n];
    const float px = centers[n * 3 + 0];
    const float py = centers[n * 3 + 1];
    const float pz = centers[n * 3 + 2];

    const float* tr = Tr + (size_t)b * 16;
    const float c0 = tr[0]  * px + tr[1]  * py + tr[2]  * pz + tr[3];
    const float c1 = tr[4]  * px + tr[5]  * py + tr[6]  * pz + tr[7];
    const float c2 = tr[8]  * px + tr[9]  * py + tr[10] * pz + tr[11];
    const float c3 = tr[12] * px + tr[13] * py + tr[14] * pz + tr[15];

    const float* r = R0 + (size_t)b * 16;
    const float e0 = r[0]  * c0 + r[1]  * c1 + r[2]  * c2 + r[3]  * c3;
    const float e1 = r[4]  * c0 + r[5]  * c1 + r[6]  * c2 + r[7]  * c3;
    const float e2 = r[8]  * c0 + r[9]  * c1 + r[10] * c2 + r[11] * c3;
    const float e3 = r[12] * c0 + r[13] * c1 + r[14] * c2 + r[15] * c3;

    const float* pm = P2 + (size_t)b * 12;
    const float iu = pm[0] * e0 + pm[1] * e1 + pm[2]  * e2 + pm[3]  * e3;
    const float iv = pm[4] * e0 + pm[5] * e1 + pm[6]  * e2 + pm[7]  * e3;
    const float iz = pm[8] * e0 + pm[9] * e1 + pm[10] * e2 + pm[11] * e3;

    const float depth = fmaxf(iz, 1e-5f);
    const float u = iu / depth;
    const float v = iv / depth;

    const int Wf = wp[0];
    const int Hf = hp[0];
    const bool valid = (iz > 0.f) && (u >= 0.f) && (u < (float)Wf) &&
                       (v >= 0.f) && (v < (float)Hf);

    const float x0f = floorf(u), y0f = floorf(v);
    const float wx1 = u - x0f, wx0 = 1.f - wx1;
    const float wy1 = v - y0f, wy0 = 1.f - wy1;
    const float vw = valid ? 1.f : 0.f;

    const float x1f = x0f + 1.f, y1f = y0f + 1.f;
    const bool bx0 = (x0f >= 0.f) && (x0f <= (float)(Wf - 1));
    const bool bx1 = (x1f >= 0.f) && (x1f <= (float)(Wf - 1));
    const bool by0 = (y0f >= 0.f) && (y0f <= (float)(Hf - 1));
    const bool by1 = (y1f >= 0.f) && (y1f <= (float)(Hf - 1));

    const float w00 = wx0 * wy0 * vw * (float)(bx0 && by0);
    const float w10 = wx1 * wy0 * vw * (float)(bx1 && by0);
    const float w01 = wx0 * wy1 * vw * (float)(bx0 && by1);
    const float w11 = wx1 * wy1 * vw * (float)(bx1 && by1);

    const int x0c = min(max((int)x0f, 0), Wf - 1);
    const int x1c = min(max((int)x0f + 1, 0), Wf - 1);
    const int y0c = min(max((int)y0f, 0), Hf - 1);
    const int y1c = min(max((int)y0f + 1, 0), Hf - 1);

    const int base_b = b * Hf * Wf;
    g_wts[n]  = make_float4(w00, w10, w01, w11);
    g_offs[n] = make_int4((base_b + y0c * Wf + x0c) * C_PT,
                          (base_b + y0c * Wf + x1c) * C_PT,
                          (base_b + y1c * Wf + x0c) * C_PT,
                          (base_b + y1c * Wf + x1c) * C_PT);
}

// ---------------------------------------------------------------------------
// Phase 2b: streaming blend: out = pf + bias + sum_i w_i * G[off_i]
// 64 threads per point (4 channels each), 4 points per block.
// ---------------------------------------------------------------------------
__global__ void blend_kernel(
    const float* __restrict__ pf,
    const float* __restrict__ ab,
    float*       __restrict__ out,
    int N)
{
    const int tid  = threadIdx.x;
    const int grp  = tid >> 6;
    const int lane = tid & 63;
    const int n = blockIdx.x * 4 + grp;
    if (n >= N) return;

    const float4 w = g_wts[n];
    const int4   o = g_offs[n];

    const int co = lane * 4;
    float4 acc = *reinterpret_cast<const float4*>(pf + (size_t)n * C_PT + co);
    const float4 bb = *reinterpret_cast<const float4*>(ab + co);
    acc.x += bb.x; acc.y += bb.y; acc.z += bb.z; acc.w += bb.w;

    if (w.x != 0.f) {
        const float4 gv = *reinterpret_cast<const float4*>(g_G + o.x + co);
        acc.x = fmaf(w.x, gv.x, acc.x); acc.y = fmaf(w.x, gv.y, acc.y);
        acc.z = fmaf(w.x, gv.z, acc.z); acc.w = fmaf(w.x, gv.w, acc.w);
    }
    if (w.y != 0.f) {
        const float4 gv = *reinterpret_cast<const float4*>(g_G + o.y + co);
        acc.x = fmaf(w.y, gv.x, acc.x); acc.y = fmaf(w.y, gv.y, acc.y);
        acc.z = fmaf(w.y, gv.z, acc.z); acc.w = fmaf(w.y, gv.w, acc.w);
    }
    if (w.z != 0.f) {
        const float4 gv = *reinterpret_cast<const float4*>(g_G + o.z + co);
        acc.x = fmaf(w.z, gv.x, acc.x); acc.y = fmaf(w.z, gv.y, acc.y);
        acc.z = fmaf(w.z, gv.z, acc.z); acc.w = fmaf(w.z, gv.w, acc.w);
    }
    if (w.w != 0.f) {
        const float4 gv = *reinterpret_cast<const float4*>(g_G + o.w + co);
        acc.x = fmaf(w.w, gv.x, acc.x); acc.y = fmaf(w.w, gv.y, acc.y);
        acc.z = fmaf(w.w, gv.z, acc.z); acc.w = fmaf(w.w, gv.w, acc.w);
    }

    *reinterpret_cast<float4*>(out + (size_t)n * C_PT + co) = acc;
}

// ---------------------------------------------------------------------------
// Launch
// Input order (metadata): point_feat, pillar_centers, img_feat, P2, R0, Tr,
//                         align_w, align_b, batch_idx, img_h, img_w
// ---------------------------------------------------------------------------
extern "C" void kernel_launch(void* const* d_in, const int* in_sizes, int n_in,
                              void* d_out, int out_size) {
    const float* point_feat = (const float*)d_in[0];
    const float* centers    = (const float*)d_in[1];
    const float* img        = (const float*)d_in[2];
    const float* P2         = (const float*)d_in[3];
    const float* R0         = (const float*)d_in[4];
    const float* Tr         = (const float*)d_in[5];
    const float* align_w    = (const float*)d_in[6];
    const float* align_b    = (const float*)d_in[7];
    const int*   bidx       = (const int*)d_in[8];
    const int*   img_h      = (const int*)d_in[9];
    const int*   img_w      = (const int*)d_in[10];
    float* out = (float*)d_out;

    const int N  = in_sizes[8];
    const int BS = in_sizes[3] / 12;
    const int HW = in_sizes[2] / (BS * C_IMG);
    const int M  = BS * HW;

    cudaFuncSetAttribute(gemm_mma, cudaFuncAttributeMaxDynamicSharedMemorySize, GEMM_SMEM);

    // Phase 0: W^T (tf32-rounded)
    transpose_w<<<dim3(C_IMG / 32, C_PT / 32), dim3(32, 8)>>>(align_w);

    // Phase 2a can run concurrently with the GEMM's dependencies (same stream:
    // just cheap; ~4us) — issue early so blend only waits on gemm.
    proj_kernel<<<(N + 255) / 256, 256>>>(centers, P2, R0, Tr, bidx, img_h, img_w, N);

    // Phase 1: G = img @ W^T via mma.sync tf32 (3-stage cp.async)
    gemm_mma<<<dim3(M / BM, C_PT / BN), 256, GEMM_SMEM>>>(img, HW);

    // Phase 2b: streaming blend
    blend_kernel<<<(N + 3) / 4, 256>>>(point_feat, align_b, out, N);
}